// round 14
// baseline (speedup 1.0000x reference)
#include <cuda_runtime.h>
#include <cuda_fp16.h>
#include <cstdint>
#include <cstddef>

// ---------------- problem constants ----------------
#define NB      32
#define T_STEP  16
#define NPATCH  49
#define SEQL    784            // T_STEP * NUM_PATCHES
#define TOK     25088          // NB * SEQL
#define DIM     512
#define HEADS   8
#define DH      64
#define MLPD    2048
#define PDIM    432
#define PDIMP   448            // padded to a multiple of 32
#define DEPTH   4

// ---------------- scratch (device globals; no allocations allowed) ----------------
__device__ int    g_s0 [NB];
__device__ float  g_pm [(size_t)NB * 8 * DIM];
__device__ __half g_x16  [(size_t)TOK * DIM];
__device__ __half g_qkv16[(size_t)TOK * 3 * DIM];
__device__ __half g_h16  [(size_t)TOK * DIM];
__device__ __half g_att16[(size_t)TOK * DIM];
__device__ __half g_mlp16[(size_t)TOK * MLPD];
__device__ __half g_p16  [(size_t)TOK * PDIMP];

// transposed fp16 weights  [N][K] layouts (element offsets)
#define OFF_QKVT 0
#define OFF_WOT  3145728
#define OFF_W1T  4194304
#define OFF_W2T  8388608
#define OFF_WEBT 12582912
__device__ __half g_w16[12812288];

// ---------------- epilogue modes ----------------
#define EPI_NONE  0
#define EPI_EMBED 1
#define EPI_RES   2
#define EPI_GELU  3

// ---------------- helpers ----------------
__device__ __forceinline__ uint32_t smem_u32(const void* p) {
    uint32_t a;
    asm("{ .reg .u64 t; cvta.to.shared.u64 t, %1; cvt.u32.u64 %0, t; }" : "=r"(a) : "l"(p));
    return a;
}

__device__ __forceinline__ void mma_f16(float c[4], const uint32_t a[4], const uint32_t b[2]) {
    asm volatile(
        "mma.sync.aligned.m16n8k16.row.col.f32.f16.f16.f32 "
        "{%0,%1,%2,%3}, {%4,%5,%6,%7}, {%8,%9}, {%0,%1,%2,%3};\n"
        : "+f"(c[0]), "+f"(c[1]), "+f"(c[2]), "+f"(c[3])
        : "r"(a[0]), "r"(a[1]), "r"(a[2]), "r"(a[3]), "r"(b[0]), "r"(b[1]));
}

__device__ __forceinline__ void ldsm_x4(uint32_t& r0, uint32_t& r1, uint32_t& r2,
                                        uint32_t& r3, uint32_t addr) {
    asm volatile("ldmatrix.sync.aligned.m8n8.x4.shared.b16 {%0,%1,%2,%3}, [%4];"
                 : "=r"(r0), "=r"(r1), "=r"(r2), "=r"(r3) : "r"(addr));
}

#define CP_ASYNC16(dst, src) \
    asm volatile("cp.async.cg.shared.global [%0], [%1], 16;" :: "r"(dst), "l"(src))
#define CP_COMMIT() asm volatile("cp.async.commit_group;" ::: "memory")
#define CP_WAIT2()  asm volatile("cp.async.wait_group 2;" ::: "memory")

// swizzled 16B-unit offset in a 128-row x 64B-row operand tile
__device__ __forceinline__ uint32_t swz16(int m, int q) {
    return (uint32_t)(m * 4 + (q ^ ((m >> 1) & 3)));
}

// ---------------- episodic mask suffix start ----------------
__global__ void s0_kernel(const int* __restrict__ done, int* __restrict__ s0)
{
    int n = threadIdx.x;
    if (n >= NB) return;
    int last = -1;
    for (int t = 0; t < T_STEP - 1; ++t)
        if (done[n * (T_STEP - 1) + t]) last = t;
    s0[n] = (last + 1) * NPATCH;
}

// ---------------- partial V sums (fp16 qkv -> f32 sums) ----------------
__global__ void pmean_kernel(const __half* __restrict__ qkv, float* __restrict__ pm)
{
    const int part = blockIdx.x;   // 0..7
    const int n = blockIdx.y;
    const int d = threadIdx.x;     // 512
    const __half* base = qkv + (size_t)n * SEQL * (3 * DIM) + 2 * DIM + d;
    const int r0 = part * 98;
    float s = 0.f;
#pragma unroll 7
    for (int r = 0; r < 98; ++r)
        s += __half2float(base[(size_t)(r0 + r) * (3 * DIM)]);
    pm[((size_t)n * 8 + part) * DIM + d] = s;
}

// ---------------- patch -> fp16 with zero pad to PDIMP ----------------
__global__ void cvt_patch_kernel(const float* __restrict__ p, __half* __restrict__ o)
{
    const int idx = blockIdx.x * 256 + threadIdx.x;        // TOK*PDIMP total
    const int tok = idx / PDIMP;
    const int c = idx % PDIMP;
    o[idx] = (c < PDIM) ? __float2half(p[(size_t)tok * PDIM + c]) : __half(0.f);
}

// ---------------- weight transpose: src[K][N] f32 -> dst[N][Kd] fp16 ----------
__global__ void transpose_kernel(const float* __restrict__ src0, __half* __restrict__ dst0,
                                 int K, int N, int Kd)
{
    const float* src = src0 + (size_t)blockIdx.z * K * N;
    __half* dst = dst0 + (size_t)blockIdx.z * N * Kd;
    __shared__ float t[32][33];
    int x = blockIdx.x * 32 + threadIdx.x;   // n
    int y = blockIdx.y * 32 + threadIdx.y;   // k
#pragma unroll
    for (int j = 0; j < 32; j += 8)
        if (x < N && y + j < K)
            t[threadIdx.y + j][threadIdx.x] = src[(size_t)(y + j) * N + x];
    __syncthreads();
    x = blockIdx.y * 32 + threadIdx.x;       // k
    y = blockIdx.x * 32 + threadIdx.y;       // n
#pragma unroll
    for (int j = 0; j < 32; j += 8)
        if (x < K && y + j < N)
            dst[(size_t)(y + j) * Kd + x] = __float2half(t[threadIdx.x][threadIdx.y + j]);
}

// ---------------- fp16 mma.sync GEMM, cp.async 4-stage pipeline, BK=32 ----------
// (round-10 design) 128x128 CTA tile, 256 threads, warp tile 64x32.
// smem: 4 stages x (A 8KB + B 8KB) = 64KB. fp32 accumulate. Requires K%32==0.
// Residual operand (res16) and output (Ch) are fp16.
#define GSTAGE 16384u
#define TG_SMEM (4 * 16384)
__global__ __launch_bounds__(256, 2)
void tgemm_kernel(const __half* __restrict__ A, const __half* __restrict__ Bt,
                  const float* __restrict__ bias, const __half* __restrict__ res16,
                  __half* __restrict__ Ch,
                  int M, int N, int K, int epi,
                  const float* __restrict__ sp, const float* __restrict__ tp)
{
    extern __shared__ __align__(16) uint8_t smraw[];

    const int tid = threadIdx.x;
    const int lane = tid & 31;
    const int wid = tid >> 5;
    const int warp_m = wid >> 2;
    const int warp_n = wid & 3;
    const int n0 = blockIdx.x * 128;
    const int m0 = blockIdx.y * 128;

    const int l_m = tid >> 1;          // 0..127
    const int l_u = (tid & 1) * 2;     // 16B units {0,1} or {2,3}

    const uint32_t sbase = smem_u32(smraw);
    const uint32_t dA0 = sbase + swz16(l_m, l_u) * 16;
    const uint32_t dA1 = sbase + swz16(l_m, l_u + 1) * 16;
    const uint32_t dB0 = dA0 + 8192u;
    const uint32_t dB1 = dA1 + 8192u;

    const __half* Ap = A + (size_t)(m0 + l_m) * K + l_u * 8;
    const __half* Bp = Bt + (size_t)(n0 + l_m) * K + l_u * 8;

    const int g = lane >> 3;
    const int r = lane & 7;
    const int a_mrow0 = warp_m * 64 + (g & 1) * 8 + r;
    const int a_kq = g >> 1;
    const int b_nrow0 = warp_n * 32 + (g >> 1) * 8 + r;
    const int b_kq = g & 1;

    float acc[4][4][4];
#pragma unroll
    for (int mt = 0; mt < 4; ++mt)
#pragma unroll
        for (int nt = 0; nt < 4; ++nt)
#pragma unroll
            for (int e = 0; e < 4; ++e) acc[mt][nt][e] = 0.f;

    const int niter = K >> 5;          // BK = 32 halves

    // prologue: stages 0,1,2
#pragma unroll
    for (int p = 0; p < 3; ++p) {
        const int ko = p * 32;
        const uint32_t so = (uint32_t)p * GSTAGE;
        CP_ASYNC16(dA0 + so, Ap + ko);
        CP_ASYNC16(dA1 + so, Ap + ko + 8);
        CP_ASYNC16(dB0 + so, Bp + ko);
        CP_ASYNC16(dB1 + so, Bp + ko + 8);
        CP_COMMIT();
    }

    int st = 0;
    for (int i = 0; i < niter; ++i) {
        CP_WAIT2();
        __syncthreads();

        if (i + 3 < niter) {
            const int ko = (i + 3) * 32;
            const uint32_t so = (uint32_t)((st + 3) & 3) * GSTAGE;
            CP_ASYNC16(dA0 + so, Ap + ko);
            CP_ASYNC16(dA1 + so, Ap + ko + 8);
            CP_ASYNC16(dB0 + so, Bp + ko);
            CP_ASYNC16(dB1 + so, Bp + ko + 8);
        }
        CP_COMMIT();

        const uint32_t sA = sbase + (uint32_t)st * GSTAGE;
        const uint32_t sB = sA + 8192u;

#pragma unroll
        for (int ks = 0; ks < 2; ++ks) {        // two k16 steps per BK=32
            uint32_t af[4][4];
            uint32_t bf[4][2];
#pragma unroll
            for (int mt = 0; mt < 4; ++mt) {
                const int mrow = a_mrow0 + mt * 16;
                const uint32_t addr = sA + swz16(mrow, ks * 2 + a_kq) * 16;
                ldsm_x4(af[mt][0], af[mt][1], af[mt][2], af[mt][3], addr);
            }
#pragma unroll
            for (int p = 0; p < 2; ++p) {
                const int nrow = b_nrow0 + p * 16;
                const uint32_t addr = sB + swz16(nrow, ks * 2 + b_kq) * 16;
                ldsm_x4(bf[p * 2][0], bf[p * 2][1], bf[p * 2 + 1][0], bf[p * 2 + 1][1], addr);
            }
#pragma unroll
            for (int mt = 0; mt < 4; ++mt)
#pragma unroll
                for (int nt = 0; nt < 4; ++nt)
                    mma_f16(acc[mt][nt], af[mt], bf[nt]);
        }
        st = (st + 1) & 3;
    }

    // -------- epilogue --------
    const int r_base = m0 + warp_m * 64;
    const int c_base = n0 + warp_n * 32;
    const int rl = lane >> 2;
    const int cl = (lane & 3) * 2;

#pragma unroll
    for (int mt = 0; mt < 4; ++mt) {
#pragma unroll
        for (int half = 0; half < 2; ++half) {
            const int rr = r_base + mt * 16 + rl + half * 8;
            const int l = rr % SEQL;
            const int tt = l / NPATCH;
            const int pp = l % NPATCH;
#pragma unroll
            for (int nt = 0; nt < 4; ++nt) {
                const int col = c_base + nt * 8 + cl;
                float v0 = acc[mt][nt][half * 2 + 0] + bias[col];
                float v1 = acc[mt][nt][half * 2 + 1] + bias[col + 1];
                if (epi == EPI_EMBED) {
                    v0 += sp[(size_t)pp * DIM + col]     + tp[(size_t)tt * DIM + col];
                    v1 += sp[(size_t)pp * DIM + col + 1] + tp[(size_t)tt * DIM + col + 1];
                } else if (epi == EPI_RES) {
                    const __half2 r2 = *(const __half2*)(res16 + (size_t)rr * N + col);
                    const float2 rf = __half22float2(r2);
                    v0 += rf.x;
                    v1 += rf.y;
                } else if (epi == EPI_GELU) {
                    v0 = 0.5f * v0 * (1.0f + erff(v0 * 0.70710678118654752f));
                    v1 = 0.5f * v1 * (1.0f + erff(v1 * 0.70710678118654752f));
                }
                *(__half2*)(Ch + (size_t)rr * N + col) = __floats2half2_rn(v0, v1);
            }
        }
    }
}

// ---------------- LayerNorm: one WARP per row of 512 (fp16 in), templated out ------
template <bool HOUT>
__global__ __launch_bounds__(256)
void ln_kernel(const __half* __restrict__ x, const float* __restrict__ g,
               const float* __restrict__ b, float* __restrict__ yf,
               __half* __restrict__ yh)
{
    const int row = blockIdx.x * 8 + (threadIdx.x >> 5);
    const int lane = threadIdx.x & 31;
    const __half* xr = x + (size_t)row * DIM;

    // 16 halves per lane: cols [lane*8, lane*8+8) and [256+lane*8, ...)
    float v[16];
#pragma unroll
    for (int gix = 0; gix < 2; ++gix) {
        const uint4 u = *(const uint4*)(xr + gix * 256 + lane * 8);
        const __half2* hp = (const __half2*)&u;
#pragma unroll
        for (int k = 0; k < 4; ++k) {
            const float2 f = __half22float2(hp[k]);
            v[gix * 8 + 2 * k]     = f.x;
            v[gix * 8 + 2 * k + 1] = f.y;
        }
    }

    float s = 0.f;
#pragma unroll
    for (int k = 0; k < 16; ++k) s += v[k];
#pragma unroll
    for (int o = 16; o > 0; o >>= 1) s += __shfl_xor_sync(0xffffffffu, s, o);
    const float mean = s * (1.0f / DIM);

    float q = 0.f;
#pragma unroll
    for (int k = 0; k < 16; ++k) {
        const float d = v[k] - mean;
        q += d * d;
    }
#pragma unroll
    for (int o = 16; o > 0; o >>= 1) q += __shfl_xor_sync(0xffffffffu, q, o);
    const float rs = rsqrtf(q * (1.0f / DIM) + 1e-5f);

#pragma unroll
    for (int gix = 0; gix < 2; ++gix) {
        const int col = gix * 256 + lane * 8;
        float ov[8];
#pragma unroll
        for (int k = 0; k < 8; ++k) {
            const float gv = g[col + k];
            const float bv = b[col + k];
            ov[k] = (v[gix * 8 + k] - mean) * rs * gv + bv;
        }
        if (HOUT) {
            __half2 h[4];
#pragma unroll
            for (int k = 0; k < 4; ++k)
                h[k] = __floats2half2_rn(ov[2 * k], ov[2 * k + 1]);
            *(uint4*)(yh + (size_t)row * DIM + col) = *(uint4*)h;
        } else {
            *(float4*)(yf + (size_t)row * DIM + col) =
                make_float4(ov[0], ov[1], ov[2], ov[3]);
            *(float4*)(yf + (size_t)row * DIM + col + 4) =
                make_float4(ov[4], ov[5], ov[6], ov[7]);
        }
    }
}

// ---------------- flash attention over the kept suffix; masked rows filled here --------
// Softmax parallelized: 4 threads per row (16 entries each), shfl-combined.
#define AT   64
#define APAD 68
__global__ __launch_bounds__(256)
void attn_kernel(const __half* __restrict__ qkv, const int* __restrict__ s0arr,
                 const float* __restrict__ pm, __half* __restrict__ out)
{
    const int qt = blockIdx.x;
    const int h  = blockIdx.y;
    const int n  = blockIdx.z;
    const int q0 = qt * AT;
    const int s0n = s0arr[n];
    const bool full_masked = (q0 + AT <= s0n);
    if (full_masked && h != 0) return;

    extern __shared__ float sm[];

    const int tid = threadIdx.x;

    // ---- masked-row fill (h==0 only): rows [q0, min(s0n, q0+AT)) get meanV ----
    if (h == 0 && q0 < s0n) {
        float* mv = sm;               // 512 floats scratch
#pragma unroll
        for (int it = 0; it < 2; ++it) {
            const int d = tid + it * 256;
            float s = 0.f;
#pragma unroll
            for (int p = 0; p < 8; ++p)
                s += pm[((size_t)n * 8 + p) * DIM + d];
            mv[d] = s * (1.0f / 784.0f);
        }
        __syncthreads();
        const int ms = (s0n < q0 + AT ? s0n : q0 + AT);
        const int nrows = ms - q0;
        __half* ob = out + ((size_t)n * SEQL + q0) * DIM;
        for (int idx = tid; idx < nrows * DIM; idx += 256) {
            const int d = idx & (DIM - 1);
            ob[idx] = __float2half(mv[d]);
        }
        __syncthreads();
    }
    if (full_masked) return;

    float* Qt   = sm;
    float* Kt   = Qt + AT * APAD;
    float* Vs   = Kt + AT * APAD;
    float* Ps   = Vs + AT * APAD;
    float* mrow = Ps + AT * APAD;
    float* lrow = mrow + AT;
    float* crow = lrow + AT;

    const int tx = tid & 15;
    const int ty = tid >> 4;
    const int tx4 = tx * 4, ty4 = ty * 4;

    const __half* base = qkv + (size_t)n * SEQL * (3 * DIM);

    // load Q tile (transposed into Qt[d][q]); 8 halves per thread-iter
#pragma unroll
    for (int it = 0; it < 2; ++it) {
        int idx = tid + it * 256;
        int row = idx >> 3;
        int cg  = (idx & 7) * 8;
        int qrow = q0 + row;
        int src = qrow < SEQL ? qrow : (SEQL - 1);
        uint4 u = *(const uint4*)(base + (size_t)src * (3 * DIM) + h * DH + cg);
        const __half2* hp = (const __half2*)&u;
#pragma unroll
        for (int k = 0; k < 4; ++k) {
            float2 f = __half22float2(hp[k]);
            Qt[(cg + 2 * k) * APAD + row] = f.x;
            Qt[(cg + 2 * k + 1) * APAD + row] = f.y;
        }
    }
    if (tid < AT) {
        mrow[tid] = -1e30f;
        lrow[tid] = 0.f;
    }
    float o[4][4];
#pragma unroll
    for (int i = 0; i < 4; ++i)
#pragma unroll
        for (int j = 0; j < 4; ++j) o[i][j] = 0.f;
    __syncthreads();

    const int ktstart = (s0n / AT) * AT;

    for (int kt0 = ktstart; kt0 < SEQL; kt0 += AT) {
#pragma unroll
        for (int it = 0; it < 2; ++it) {
            int idx = tid + it * 256;
            int row = idx >> 3;
            int cg  = (idx & 7) * 8;
            int krow = kt0 + row;
            int src = krow < SEQL ? krow : (SEQL - 1);
            uint4 ku = *(const uint4*)(base + (size_t)src * (3 * DIM) + DIM + h * DH + cg);
            const __half2* kp = (const __half2*)&ku;
#pragma unroll
            for (int k = 0; k < 4; ++k) {
                float2 f = __half22float2(kp[k]);
                Kt[(cg + 2 * k) * APAD + row] = f.x;
                Kt[(cg + 2 * k + 1) * APAD + row] = f.y;
            }
            uint4 vu = *(const uint4*)(base + (size_t)src * (3 * DIM) + 2 * DIM + h * DH + cg);
            const __half2* vp = (const __half2*)&vu;
            float4 vlo = make_float4(__half22float2(vp[0]).x, __half22float2(vp[0]).y,
                                     __half22float2(vp[1]).x, __half22float2(vp[1]).y);
            float4 vhi = make_float4(__half22float2(vp[2]).x, __half22float2(vp[2]).y,
                                     __half22float2(vp[3]).x, __half22float2(vp[3]).y);
            *(float4*)&Vs[row * APAD + cg] = vlo;
            *(float4*)&Vs[row * APAD + cg + 4] = vhi;
        }
        __syncthreads();

        float s[4][4];
#pragma unroll
        for (int i = 0; i < 4; ++i)
#pragma unroll
            for (int j = 0; j < 4; ++j) s[i][j] = 0.f;
#pragma unroll 8
        for (int d = 0; d < DH; ++d) {
            float a[4], bb[4];
#pragma unroll
            for (int i = 0; i < 4; ++i) a[i] = Qt[d * APAD + ty4 + i];
#pragma unroll
            for (int j = 0; j < 4; ++j) bb[j] = Kt[d * APAD + tx4 + j];
#pragma unroll
            for (int i = 0; i < 4; ++i)
#pragma unroll
                for (int j = 0; j < 4; ++j)
                    s[i][j] = fmaf(a[i], bb[j], s[i][j]);
        }

#pragma unroll
        for (int i = 0; i < 4; ++i) {
#pragma unroll
            for (int j = 0; j < 4; ++j) {
                const int kidx = kt0 + tx4 + j;
                const float val = (kidx >= s0n && kidx < SEQL) ? s[i][j] * 0.125f : -1e30f;
                Ps[(ty4 + i) * APAD + tx4 + j] = val;
            }
        }
        __syncthreads();

        // online softmax: 4 threads per row, 16 entries each, shfl-combined
        {
            const int row = tid >> 2;      // 0..63
            const int sub = tid & 3;       // 0..3
            float* pr = Ps + row * APAD + sub * 16;
            float tm = -1e30f;
#pragma unroll
            for (int k = 0; k < 16; ++k) tm = fmaxf(tm, pr[k]);
            tm = fmaxf(tm, __shfl_xor_sync(0xffffffffu, tm, 1));
            tm = fmaxf(tm, __shfl_xor_sync(0xffffffffu, tm, 2));
            const float mo = mrow[row];
            const float mn = fmaxf(mo, tm);
            float srow = 0.f;
#pragma unroll
            for (int k = 0; k < 16; ++k) {
                const float pv = pr[k];
                const float e = (pv <= -1e29f) ? 0.f : __expf(pv - mn);
                pr[k] = e;
                srow += e;
            }
            srow += __shfl_xor_sync(0xffffffffu, srow, 1);
            srow += __shfl_xor_sync(0xffffffffu, srow, 2);
            if (sub == 0) {
                const float c = __expf(mo - mn);
                lrow[row] = lrow[row] * c + srow;
                mrow[row] = mn;
                crow[row] = c;
            }
        }
        __syncthreads();

        float ci[4];
#pragma unroll
        for (int i = 0; i < 4; ++i) ci[i] = crow[ty4 + i];
#pragma unroll
        for (int i = 0; i < 4; ++i)
#pragma unroll
            for (int j = 0; j < 4; ++j) o[i][j] *= ci[i];
#pragma unroll 8
        for (int k = 0; k < AT; ++k) {
            float p[4], vv[4];
#pragma unroll
            for (int i = 0; i < 4; ++i) p[i] = Ps[(ty4 + i) * APAD + k];
#pragma unroll
            for (int j = 0; j < 4; ++j) vv[j] = Vs[k * APAD + tx4 + j];
#pragma unroll
            for (int i = 0; i < 4; ++i)
#pragma unroll
                for (int j = 0; j < 4; ++j)
                    o[i][j] = fmaf(p[i], vv[j], o[i][j]);
        }
        __syncthreads();
    }

#pragma unroll
    for (int i = 0; i < 4; ++i) {
        const int q = q0 + ty4 + i;
        if (q < SEQL && q >= s0n) {
            const float inv = 1.0f / lrow[ty4 + i];
            __half* op = out + ((size_t)n * SEQL + q) * DIM + h * DH + tx4;
            *(__half2*)(op)     = __floats2half2_rn(o[i][0] * inv, o[i][1] * inv);
            *(__half2*)(op + 2) = __floats2half2_rn(o[i][2] * inv, o[i][3] * inv);
        }
    }
}

#define ATT_SMEM ((4 * AT * APAD + 3 * AT) * (int)sizeof(float))

// ---------------- orchestration ----------------
extern "C" void kernel_launch(void* const* d_in, const int* in_sizes, int n_in,
                              void* d_out, int out_size)
{
    (void)in_sizes; (void)n_in; (void)out_size;
    const float* patch    = (const float*)d_in[0];
    const int*   done     = (const int*)  d_in[1];
    const float* W_embed  = (const float*)d_in[2];
    const float* b_embed  = (const float*)d_in[3];
    const float* spatial  = (const float*)d_in[4];
    const float* temporal = (const float*)d_in[5];
    const float* ln1_g    = (const float*)d_in[6];
    const float* ln1_b    = (const float*)d_in[7];
    const float* Wqkv     = (const float*)d_in[8];
    const float* bqkv     = (const float*)d_in[9];
    const float* Wo       = (const float*)d_in[10];
    const float* bo       = (const float*)d_in[11];
    const float* ln2_g    = (const float*)d_in[12];
    const float* ln2_b    = (const float*)d_in[13];
    const float* W1       = (const float*)d_in[14];
    const float* b1       = (const float*)d_in[15];
    const float* W2       = (const float*)d_in[16];
    const float* b2       = (const float*)d_in[17];
    const float* out_g    = (const float*)d_in[18];
    const float* out_b    = (const float*)d_in[19];
    float* out = (float*)d_out;

    float* pm;
    __half *x16, *qkv16, *h16, *att16, *mlp16, *p16, *w16;
    int* s0;
    cudaGetSymbolAddress((void**)&pm,    g_pm);
    cudaGetSymbolAddress((void**)&s0,    g_s0);
    cudaGetSymbolAddress((void**)&x16,   g_x16);
    cudaGetSymbolAddress((void**)&qkv16, g_qkv16);
    cudaGetSymbolAddress((void**)&h16,   g_h16);
    cudaGetSymbolAddress((void**)&att16, g_att16);
    cudaGetSymbolAddress((void**)&mlp16, g_mlp16);
    cudaGetSymbolAddress((void**)&p16,   g_p16);
    cudaGetSymbolAddress((void**)&w16,   g_w16);

    cudaFuncSetAttribute(attn_kernel, cudaFuncAttributeMaxDynamicSharedMemorySize, ATT_SMEM);
    cudaFuncSetAttribute(tgemm_kernel, cudaFuncAttributeMaxDynamicSharedMemorySize, TG_SMEM);

    __half* qkvT = w16 + OFF_QKVT;
    __half* woT  = w16 + OFF_WOT;
    __half* w1T  = w16 + OFF_W1T;
    __half* w2T  = w16 + OFF_W2T;
    __half* webT = w16 + OFF_WEBT;

    // weight transposes ([K][N] f32 -> [N][Kd] fp16), batched over layers
    dim3 tb(32, 8);
    transpose_kernel<<<dim3(16, 14, 1), tb>>>(W_embed, webT, PDIM, DIM, PDIMP);
    transpose_kernel<<<dim3(48, 16, DEPTH), tb>>>(Wqkv, qkvT, DIM, 3 * DIM, DIM);
    transpose_kernel<<<dim3(16, 16, DEPTH), tb>>>(Wo, woT, DIM, DIM, DIM);
    transpose_kernel<<<dim3(64, 16, DEPTH), tb>>>(W1, w1T, DIM, MLPD, DIM);
    transpose_kernel<<<dim3(16, 64, DEPTH), tb>>>(W2, w2T, MLPD, DIM, MLPD);

    s0_kernel<<<1, 32>>>(done, s0);
    cvt_patch_kernel<<<(TOK * PDIMP) / 256, 256>>>(patch, p16);

    // patch embed + pos embed -> fp16 residual stream
    tgemm_kernel<<<dim3(DIM / 128, TOK / 128), 256, TG_SMEM>>>(
        p16, webT, b_embed, nullptr, x16, TOK, DIM, PDIMP, EPI_EMBED,
        spatial, temporal);

    for (int i = 0; i < DEPTH; ++i) {
        ln_kernel<true><<<TOK / 8, 256>>>(x16, ln1_g + (size_t)i * DIM,
                                          ln1_b + (size_t)i * DIM, nullptr, h16);

        tgemm_kernel<<<dim3(3 * DIM / 128, TOK / 128), 256, TG_SMEM>>>(
            h16, qkvT + (size_t)i * 3 * DIM * DIM, bqkv + (size_t)i * 3 * DIM,
            nullptr, qkv16, TOK, 3 * DIM, DIM, EPI_NONE, nullptr, nullptr);

        pmean_kernel<<<dim3(8, NB), 512>>>(qkv16, pm);
        attn_kernel<<<dim3((SEQL + AT - 1) / AT, HEADS, NB), 256, ATT_SMEM>>>(
            qkv16, s0, pm, att16);

        tgemm_kernel<<<dim3(DIM / 128, TOK / 128), 256, TG_SMEM>>>(
            att16, woT + (size_t)i * DIM * DIM, bo + (size_t)i * DIM,
            x16, x16, TOK, DIM, DIM, EPI_RES, nullptr, nullptr);

        ln_kernel<true><<<TOK / 8, 256>>>(x16, ln2_g + (size_t)i * DIM,
                                          ln2_b + (size_t)i * DIM, nullptr, h16);

        tgemm_kernel<<<dim3(MLPD / 128, TOK / 128), 256, TG_SMEM>>>(
            h16, w1T + (size_t)i * DIM * MLPD, b1 + (size_t)i * MLPD,
            nullptr, mlp16, TOK, MLPD, DIM, EPI_GELU, nullptr, nullptr);

        tgemm_kernel<<<dim3(DIM / 128, TOK / 128), 256, TG_SMEM>>>(
            mlp16, w2T + (size_t)i * MLPD * DIM, b2 + (size_t)i * DIM,
            x16, x16, TOK, DIM, MLPD, EPI_RES, nullptr, nullptr);
    }

    ln_kernel<false><<<TOK / 8, 256>>>(x16, out_g, out_b, out, nullptr);
}

// round 15
// speedup vs baseline: 1.0537x; 1.0537x over previous
#include <cuda_runtime.h>
#include <cuda_fp16.h>
#include <cstdint>
#include <cstddef>

// ---------------- problem constants ----------------
#define NB      32
#define T_STEP  16
#define NPATCH  49
#define SEQL    784            // T_STEP * NUM_PATCHES
#define TOK     25088          // NB * SEQL
#define DIM     512
#define HEADS   8
#define DH      64
#define MLPD    2048
#define PDIM    432
#define PDIMP   448            // padded to a multiple of 32
#define DEPTH   4

// ---------------- scratch (device globals; no allocations allowed) ----------------
__device__ float  g_x  [(size_t)TOK * DIM];
__device__ int    g_s0 [NB];
__device__ float  g_pm [(size_t)NB * 8 * DIM];
__device__ __half g_qkv16[(size_t)TOK * 3 * DIM];
__device__ __half g_h16  [(size_t)TOK * DIM];
__device__ __half g_att16[(size_t)TOK * DIM];
__device__ __half g_mlp16[(size_t)TOK * MLPD];
__device__ __half g_p16  [(size_t)TOK * PDIMP];

// transposed fp16 weights  [N][K] layouts (element offsets)
#define OFF_QKVT 0
#define OFF_WOT  3145728
#define OFF_W1T  4194304
#define OFF_W2T  8388608
#define OFF_WEBT 12582912
__device__ __half g_w16[12812288];

// ---------------- epilogue modes ----------------
#define EPI_NONE  0
#define EPI_EMBED 1
#define EPI_RES   2
#define EPI_GELU  3

// ---------------- helpers ----------------
__device__ __forceinline__ uint32_t smem_u32(const void* p) {
    uint32_t a;
    asm("{ .reg .u64 t; cvta.to.shared.u64 t, %1; cvt.u32.u64 %0, t; }" : "=r"(a) : "l"(p));
    return a;
}

__device__ __forceinline__ void mma_f16(float c[4], const uint32_t a[4], const uint32_t b[2]) {
    asm volatile(
        "mma.sync.aligned.m16n8k16.row.col.f32.f16.f16.f32 "
        "{%0,%1,%2,%3}, {%4,%5,%6,%7}, {%8,%9}, {%0,%1,%2,%3};\n"
        : "+f"(c[0]), "+f"(c[1]), "+f"(c[2]), "+f"(c[3])
        : "r"(a[0]), "r"(a[1]), "r"(a[2]), "r"(a[3]), "r"(b[0]), "r"(b[1]));
}

__device__ __forceinline__ void ldsm_x4(uint32_t& r0, uint32_t& r1, uint32_t& r2,
                                        uint32_t& r3, uint32_t addr) {
    asm volatile("ldmatrix.sync.aligned.m8n8.x4.shared.b16 {%0,%1,%2,%3}, [%4];"
                 : "=r"(r0), "=r"(r1), "=r"(r2), "=r"(r3) : "r"(addr));
}

#define CP_ASYNC16(dst, src) \
    asm volatile("cp.async.cg.shared.global [%0], [%1], 16;" :: "r"(dst), "l"(src))
#define CP_COMMIT() asm volatile("cp.async.commit_group;" ::: "memory")
#define CP_WAIT2()  asm volatile("cp.async.wait_group 2;" ::: "memory")

// swizzled 16B-unit offset in a 128-row x 64B-row operand tile
__device__ __forceinline__ uint32_t swz16(int m, int q) {
    return (uint32_t)(m * 4 + (q ^ ((m >> 1) & 3)));
}

// ---------------- episodic mask suffix start ----------------
__global__ void s0_kernel(const int* __restrict__ done, int* __restrict__ s0)
{
    int n = threadIdx.x;
    if (n >= NB) return;
    int last = -1;
    for (int t = 0; t < T_STEP - 1; ++t)
        if (done[n * (T_STEP - 1) + t]) last = t;
    s0[n] = (last + 1) * NPATCH;
}

// ---------------- partial V sums (fp16 qkv -> f32 sums) ----------------
__global__ void pmean_kernel(const __half* __restrict__ qkv, float* __restrict__ pm)
{
    const int part = blockIdx.x;   // 0..7
    const int n = blockIdx.y;
    const int d = threadIdx.x;     // 512
    const __half* base = qkv + (size_t)n * SEQL * (3 * DIM) + 2 * DIM + d;
    const int r0 = part * 98;
    float s = 0.f;
#pragma unroll 7
    for (int r = 0; r < 98; ++r)
        s += __half2float(base[(size_t)(r0 + r) * (3 * DIM)]);
    pm[((size_t)n * 8 + part) * DIM + d] = s;
}

// ---------------- patch -> fp16 with zero pad to PDIMP (vectorized x4) ----------------
__global__ void cvt_patch_kernel(const float* __restrict__ p, __half* __restrict__ o)
{
    const int idx = blockIdx.x * 256 + threadIdx.x;     // one 4-element group
    const int tok = idx / (PDIMP / 4);
    const int c4 = idx % (PDIMP / 4);
    __half2 h0, h1;
    if (c4 < PDIM / 4) {
        const float4 f = *(const float4*)(p + (size_t)tok * PDIM + c4 * 4);
        h0 = __floats2half2_rn(f.x, f.y);
        h1 = __floats2half2_rn(f.z, f.w);
    } else {
        h0 = __floats2half2_rn(0.f, 0.f);
        h1 = h0;
    }
    __half* ob = o + (size_t)tok * PDIMP + c4 * 4;
    *(__half2*)(ob) = h0;
    *(__half2*)(ob + 2) = h1;
}

// ---------------- weight transpose: src[K][N] f32 -> dst[N][Kd] fp16 ----------
__global__ void transpose_kernel(const float* __restrict__ src0, __half* __restrict__ dst0,
                                 int K, int N, int Kd)
{
    const float* src = src0 + (size_t)blockIdx.z * K * N;
    __half* dst = dst0 + (size_t)blockIdx.z * N * Kd;
    __shared__ float t[32][33];
    int x = blockIdx.x * 32 + threadIdx.x;   // n
    int y = blockIdx.y * 32 + threadIdx.y;   // k
#pragma unroll
    for (int j = 0; j < 32; j += 8)
        if (x < N && y + j < K)
            t[threadIdx.y + j][threadIdx.x] = src[(size_t)(y + j) * N + x];
    __syncthreads();
    x = blockIdx.y * 32 + threadIdx.x;       // k
    y = blockIdx.x * 32 + threadIdx.y;       // n
#pragma unroll
    for (int j = 0; j < 32; j += 8)
        if (x < K && y + j < N)
            dst[(size_t)(y + j) * Kd + x] = __float2half(t[threadIdx.x][threadIdx.y + j]);
}

// ---------------- fp16 mma.sync GEMM, cp.async 4-stage pipeline, BK=32 ----------
// (round-10/13 design, proven best) 128x128 CTA tile, 256 threads, warp tile 64x32.
// smem: 4 stages x (A 8KB + B 8KB) = 64KB. fp32 accumulate. Requires K%32==0.
#define GSTAGE 16384u
#define TG_SMEM (4 * 16384)
__global__ __launch_bounds__(256, 2)
void tgemm_kernel(const __half* __restrict__ A, const __half* __restrict__ Bt,
                  const float* __restrict__ bias, const float* __restrict__ res,
                  float* __restrict__ Cf, __half* __restrict__ Ch,
                  int M, int N, int K, int epi,
                  const float* __restrict__ sp, const float* __restrict__ tp)
{
    extern __shared__ __align__(16) uint8_t smraw[];

    const int tid = threadIdx.x;
    const int lane = tid & 31;
    const int wid = tid >> 5;
    const int warp_m = wid >> 2;
    const int warp_n = wid & 3;
    const int n0 = blockIdx.x * 128;
    const int m0 = blockIdx.y * 128;

    const int l_m = tid >> 1;          // 0..127
    const int l_u = (tid & 1) * 2;     // 16B units {0,1} or {2,3}

    const uint32_t sbase = smem_u32(smraw);
    const uint32_t dA0 = sbase + swz16(l_m, l_u) * 16;
    const uint32_t dA1 = sbase + swz16(l_m, l_u + 1) * 16;
    const uint32_t dB0 = dA0 + 8192u;
    const uint32_t dB1 = dA1 + 8192u;

    const __half* Ap = A + (size_t)(m0 + l_m) * K + l_u * 8;
    const __half* Bp = Bt + (size_t)(n0 + l_m) * K + l_u * 8;

    const int g = lane >> 3;
    const int r = lane & 7;
    const int a_mrow0 = warp_m * 64 + (g & 1) * 8 + r;
    const int a_kq = g >> 1;
    const int b_nrow0 = warp_n * 32 + (g >> 1) * 8 + r;
    const int b_kq = g & 1;

    float acc[4][4][4];
#pragma unroll
    for (int mt = 0; mt < 4; ++mt)
#pragma unroll
        for (int nt = 0; nt < 4; ++nt)
#pragma unroll
            for (int e = 0; e < 4; ++e) acc[mt][nt][e] = 0.f;

    const int niter = K >> 5;          // BK = 32 halves

    // prologue: stages 0,1,2
#pragma unroll
    for (int p = 0; p < 3; ++p) {
        const int ko = p * 32;
        const uint32_t so = (uint32_t)p * GSTAGE;
        CP_ASYNC16(dA0 + so, Ap + ko);
        CP_ASYNC16(dA1 + so, Ap + ko + 8);
        CP_ASYNC16(dB0 + so, Bp + ko);
        CP_ASYNC16(dB1 + so, Bp + ko + 8);
        CP_COMMIT();
    }

    int st = 0;
    for (int i = 0; i < niter; ++i) {
        CP_WAIT2();
        __syncthreads();

        if (i + 3 < niter) {
            const int ko = (i + 3) * 32;
            const uint32_t so = (uint32_t)((st + 3) & 3) * GSTAGE;
            CP_ASYNC16(dA0 + so, Ap + ko);
            CP_ASYNC16(dA1 + so, Ap + ko + 8);
            CP_ASYNC16(dB0 + so, Bp + ko);
            CP_ASYNC16(dB1 + so, Bp + ko + 8);
        }
        CP_COMMIT();

        const uint32_t sA = sbase + (uint32_t)st * GSTAGE;
        const uint32_t sB = sA + 8192u;

#pragma unroll
        for (int ks = 0; ks < 2; ++ks) {        // two k16 steps per BK=32
            uint32_t af[4][4];
            uint32_t bf[4][2];
#pragma unroll
            for (int mt = 0; mt < 4; ++mt) {
                const int mrow = a_mrow0 + mt * 16;
                const uint32_t addr = sA + swz16(mrow, ks * 2 + a_kq) * 16;
                ldsm_x4(af[mt][0], af[mt][1], af[mt][2], af[mt][3], addr);
            }
#pragma unroll
            for (int p = 0; p < 2; ++p) {
                const int nrow = b_nrow0 + p * 16;
                const uint32_t addr = sB + swz16(nrow, ks * 2 + b_kq) * 16;
                ldsm_x4(bf[p * 2][0], bf[p * 2][1], bf[p * 2 + 1][0], bf[p * 2 + 1][1], addr);
            }
#pragma unroll
            for (int mt = 0; mt < 4; ++mt)
#pragma unroll
                for (int nt = 0; nt < 4; ++nt)
                    mma_f16(acc[mt][nt], af[mt], bf[nt]);
        }
        st = (st + 1) & 3;
    }

    // -------- epilogue --------
    const int r_base = m0 + warp_m * 64;
    const int c_base = n0 + warp_n * 32;
    const int rl = lane >> 2;
    const int cl = (lane & 3) * 2;

#pragma unroll
    for (int mt = 0; mt < 4; ++mt) {
#pragma unroll
        for (int half = 0; half < 2; ++half) {
            const int rr = r_base + mt * 16 + rl + half * 8;
            const int l = rr % SEQL;
            const int tt = l / NPATCH;
            const int pp = l % NPATCH;
#pragma unroll
            for (int nt = 0; nt < 4; ++nt) {
                const int col = c_base + nt * 8 + cl;
                float v0 = acc[mt][nt][half * 2 + 0] + bias[col];
                float v1 = acc[mt][nt][half * 2 + 1] + bias[col + 1];
                if (epi == EPI_EMBED) {
                    v0 += sp[(size_t)pp * DIM + col]     + tp[(size_t)tt * DIM + col];
                    v1 += sp[(size_t)pp * DIM + col + 1] + tp[(size_t)tt * DIM + col + 1];
                } else if (epi == EPI_RES) {
                    v0 += res[(size_t)rr * N + col];
                    v1 += res[(size_t)rr * N + col + 1];
                } else if (epi == EPI_GELU) {
                    v0 = 0.5f * v0 * (1.0f + erff(v0 * 0.70710678118654752f));
                    v1 = 0.5f * v1 * (1.0f + erff(v1 * 0.70710678118654752f));
                }
                if (Ch)
                    *(__half2*)(Ch + (size_t)rr * N + col) = __floats2half2_rn(v0, v1);
                else
                    *(float2*)(Cf + (size_t)rr * N + col) = make_float2(v0, v1);
            }
        }
    }
}

// ---------------- LayerNorm: one WARP per row of 512, templated output ----------------
template <bool HOUT>
__global__ __launch_bounds__(256)
void ln_kernel(const float* __restrict__ x, const float* __restrict__ g,
               const float* __restrict__ b, float* __restrict__ yf,
               __half* __restrict__ yh)
{
    const int row = blockIdx.x * 8 + (threadIdx.x >> 5);
    const int lane = threadIdx.x & 31;
    const float* xr = x + (size_t)row * DIM;

    float4 v[4];
#pragma unroll
    for (int w = 0; w < 4; ++w)
        v[w] = *(const float4*)(xr + w * 128 + lane * 4);

    float s = 0.f;
#pragma unroll
    for (int w = 0; w < 4; ++w) s += v[w].x + v[w].y + v[w].z + v[w].w;
#pragma unroll
    for (int o = 16; o > 0; o >>= 1) s += __shfl_xor_sync(0xffffffffu, s, o);
    const float mean = s * (1.0f / DIM);

    float q = 0.f;
#pragma unroll
    for (int w = 0; w < 4; ++w) {
        const float d0 = v[w].x - mean, d1 = v[w].y - mean;
        const float d2 = v[w].z - mean, d3 = v[w].w - mean;
        q += d0 * d0 + d1 * d1 + d2 * d2 + d3 * d3;
    }
#pragma unroll
    for (int o = 16; o > 0; o >>= 1) q += __shfl_xor_sync(0xffffffffu, q, o);
    const float rs = rsqrtf(q * (1.0f / DIM) + 1e-5f);

#pragma unroll
    for (int w = 0; w < 4; ++w) {
        const int col = w * 128 + lane * 4;
        const float4 gv = *(const float4*)(g + col);
        const float4 bv = *(const float4*)(b + col);
        float4 o4;
        o4.x = (v[w].x - mean) * rs * gv.x + bv.x;
        o4.y = (v[w].y - mean) * rs * gv.y + bv.y;
        o4.z = (v[w].z - mean) * rs * gv.z + bv.z;
        o4.w = (v[w].w - mean) * rs * gv.w + bv.w;
        if (HOUT) {
            __half2 h0 = __floats2half2_rn(o4.x, o4.y);
            __half2 h1 = __floats2half2_rn(o4.z, o4.w);
            uint2 pk;
            pk.x = *(uint32_t*)&h0;
            pk.y = *(uint32_t*)&h1;
            *(uint2*)(yh + (size_t)row * DIM + col) = pk;
        } else {
            *(float4*)(yf + (size_t)row * DIM + col) = o4;
        }
    }
}

// ---------------- flash attention over the kept suffix; masked rows filled here --------
// Softmax parallelized: 4 threads per row (16 entries each), shfl-combined.
#define AT   64
#define APAD 68
__global__ __launch_bounds__(256)
void attn_kernel(const __half* __restrict__ qkv, const int* __restrict__ s0arr,
                 const float* __restrict__ pm, __half* __restrict__ out)
{
    const int qt = blockIdx.x;
    const int h  = blockIdx.y;
    const int n  = blockIdx.z;
    const int q0 = qt * AT;
    const int s0n = s0arr[n];
    const bool full_masked = (q0 + AT <= s0n);
    if (full_masked && h != 0) return;

    extern __shared__ float sm[];

    const int tid = threadIdx.x;

    // ---- masked-row fill (h==0 only): rows [q0, min(s0n, q0+AT)) get meanV ----
    if (h == 0 && q0 < s0n) {
        float* mv = sm;               // 512 floats scratch
#pragma unroll
        for (int it = 0; it < 2; ++it) {
            const int d = tid + it * 256;
            float s = 0.f;
#pragma unroll
            for (int p = 0; p < 8; ++p)
                s += pm[((size_t)n * 8 + p) * DIM + d];
            mv[d] = s * (1.0f / 784.0f);
        }
        __syncthreads();
        const int ms = (s0n < q0 + AT ? s0n : q0 + AT);
        const int nrows = ms - q0;
        __half* ob = out + ((size_t)n * SEQL + q0) * DIM;
        for (int idx = tid; idx < nrows * DIM; idx += 256) {
            const int d = idx & (DIM - 1);
            ob[idx] = __float2half(mv[d]);
        }
        __syncthreads();
    }
    if (full_masked) return;

    float* Qt   = sm;
    float* Kt   = Qt + AT * APAD;
    float* Vs   = Kt + AT * APAD;
    float* Ps   = Vs + AT * APAD;
    float* mrow = Ps + AT * APAD;
    float* lrow = mrow + AT;
    float* crow = lrow + AT;

    const int tx = tid & 15;
    const int ty = tid >> 4;
    const int tx4 = tx * 4, ty4 = ty * 4;

    const __half* base = qkv + (size_t)n * SEQL * (3 * DIM);

    // load Q tile (transposed into Qt[d][q]); 8 halves per thread-iter
#pragma unroll
    for (int it = 0; it < 2; ++it) {
        int idx = tid + it * 256;
        int row = idx >> 3;
        int cg  = (idx & 7) * 8;
        int qrow = q0 + row;
        int src = qrow < SEQL ? qrow : (SEQL - 1);
        uint4 u = *(const uint4*)(base + (size_t)src * (3 * DIM) + h * DH + cg);
        const __half2* hp = (const __half2*)&u;
#pragma unroll
        for (int k = 0; k < 4; ++k) {
            float2 f = __half22float2(hp[k]);
            Qt[(cg + 2 * k) * APAD + row] = f.x;
            Qt[(cg + 2 * k + 1) * APAD + row] = f.y;
        }
    }
    if (tid < AT) {
        mrow[tid] = -1e30f;
        lrow[tid] = 0.f;
    }
    float o[4][4];
#pragma unroll
    for (int i = 0; i < 4; ++i)
#pragma unroll
        for (int j = 0; j < 4; ++j) o[i][j] = 0.f;
    __syncthreads();

    const int ktstart = (s0n / AT) * AT;

    for (int kt0 = ktstart; kt0 < SEQL; kt0 += AT) {
#pragma unroll
        for (int it = 0; it < 2; ++it) {
            int idx = tid + it * 256;
            int row = idx >> 3;
            int cg  = (idx & 7) * 8;
            int krow = kt0 + row;
            int src = krow < SEQL ? krow : (SEQL - 1);
            uint4 ku = *(const uint4*)(base + (size_t)src * (3 * DIM) + DIM + h * DH + cg);
            const __half2* kp = (const __half2*)&ku;
#pragma unroll
            for (int k = 0; k < 4; ++k) {
                float2 f = __half22float2(kp[k]);
                Kt[(cg + 2 * k) * APAD + row] = f.x;
                Kt[(cg + 2 * k + 1) * APAD + row] = f.y;
            }
            uint4 vu = *(const uint4*)(base + (size_t)src * (3 * DIM) + 2 * DIM + h * DH + cg);
            const __half2* vp = (const __half2*)&vu;
            float4 vlo = make_float4(__half22float2(vp[0]).x, __half22float2(vp[0]).y,
                                     __half22float2(vp[1]).x, __half22float2(vp[1]).y);
            float4 vhi = make_float4(__half22float2(vp[2]).x, __half22float2(vp[2]).y,
                                     __half22float2(vp[3]).x, __half22float2(vp[3]).y);
            *(float4*)&Vs[row * APAD + cg] = vlo;
            *(float4*)&Vs[row * APAD + cg + 4] = vhi;
        }
        __syncthreads();

        float s[4][4];
#pragma unroll
        for (int i = 0; i < 4; ++i)
#pragma unroll
            for (int j = 0; j < 4; ++j) s[i][j] = 0.f;
#pragma unroll 8
        for (int d = 0; d < DH; ++d) {
            float a[4], bb[4];
#pragma unroll
            for (int i = 0; i < 4; ++i) a[i] = Qt[d * APAD + ty4 + i];
#pragma unroll
            for (int j = 0; j < 4; ++j) bb[j] = Kt[d * APAD + tx4 + j];
#pragma unroll
            for (int i = 0; i < 4; ++i)
#pragma unroll
                for (int j = 0; j < 4; ++j)
                    s[i][j] = fmaf(a[i], bb[j], s[i][j]);
        }

#pragma unroll
        for (int i = 0; i < 4; ++i) {
#pragma unroll
            for (int j = 0; j < 4; ++j) {
                const int kidx = kt0 + tx4 + j;
                const float val = (kidx >= s0n && kidx < SEQL) ? s[i][j] * 0.125f : -1e30f;
                Ps[(ty4 + i) * APAD + tx4 + j] = val;
            }
        }
        __syncthreads();

        // online softmax: 4 threads per row, 16 entries each, shfl-combined
        {
            const int row = tid >> 2;      // 0..63
            const int sub = tid & 3;       // 0..3
            float* pr = Ps + row * APAD + sub * 16;
            float tm = -1e30f;
#pragma unroll
            for (int k = 0; k < 16; ++k) tm = fmaxf(tm, pr[k]);
            tm = fmaxf(tm, __shfl_xor_sync(0xffffffffu, tm, 1));
            tm = fmaxf(tm, __shfl_xor_sync(0xffffffffu, tm, 2));
            const float mo = mrow[row];
            const float mn = fmaxf(mo, tm);
            float srow = 0.f;
#pragma unroll
            for (int k = 0; k < 16; ++k) {
                const float pv = pr[k];
                const float e = (pv <= -1e29f) ? 0.f : __expf(pv - mn);
                pr[k] = e;
                srow += e;
            }
            srow += __shfl_xor_sync(0xffffffffu, srow, 1);
            srow += __shfl_xor_sync(0xffffffffu, srow, 2);
            if (sub == 0) {
                const float c = __expf(mo - mn);
                lrow[row] = lrow[row] * c + srow;
                mrow[row] = mn;
                crow[row] = c;
            }
        }
        __syncthreads();

        float ci[4];
#pragma unroll
        for (int i = 0; i < 4; ++i) ci[i] = crow[ty4 + i];
#pragma unroll
        for (int i = 0; i < 4; ++i)
#pragma unroll
            for (int j = 0; j < 4; ++j) o[i][j] *= ci[i];
#pragma unroll 8
        for (int k = 0; k < AT; ++k) {
            float p[4], vv[4];
#pragma unroll
            for (int i = 0; i < 4; ++i) p[i] = Ps[(ty4 + i) * APAD + k];
#pragma unroll
            for (int j = 0; j < 4; ++j) vv[j] = Vs[k * APAD + tx4 + j];
#pragma unroll
            for (int i = 0; i < 4; ++i)
#pragma unroll
                for (int j = 0; j < 4; ++j)
                    o[i][j] = fmaf(p[i], vv[j], o[i][j]);
        }
        __syncthreads();
    }

#pragma unroll
    for (int i = 0; i < 4; ++i) {
        const int q = q0 + ty4 + i;
        if (q < SEQL && q >= s0n) {
            const float inv = 1.0f / lrow[ty4 + i];
            __half* op = out + ((size_t)n * SEQL + q) * DIM + h * DH + tx4;
            *(__half2*)(op)     = __floats2half2_rn(o[i][0] * inv, o[i][1] * inv);
            *(__half2*)(op + 2) = __floats2half2_rn(o[i][2] * inv, o[i][3] * inv);
        }
    }
}

#define ATT_SMEM ((4 * AT * APAD + 3 * AT) * (int)sizeof(float))

// ---------------- orchestration ----------------
extern "C" void kernel_launch(void* const* d_in, const int* in_sizes, int n_in,
                              void* d_out, int out_size)
{
    (void)in_sizes; (void)n_in; (void)out_size;
    const float* patch    = (const float*)d_in[0];
    const int*   done     = (const int*)  d_in[1];
    const float* W_embed  = (const float*)d_in[2];
    const float* b_embed  = (const float*)d_in[3];
    const float* spatial  = (const float*)d_in[4];
    const float* temporal = (const float*)d_in[5];
    const float* ln1_g    = (const float*)d_in[6];
    const float* ln1_b    = (const float*)d_in[7];
    const float* Wqkv     = (const float*)d_in[8];
    const float* bqkv     = (const float*)d_in[9];
    const float* Wo       = (const float*)d_in[10];
    const float* bo       = (const float*)d_in[11];
    const float* ln2_g    = (const float*)d_in[12];
    const float* ln2_b    = (const float*)d_in[13];
    const float* W1       = (const float*)d_in[14];
    const float* b1       = (const float*)d_in[15];
    const float* W2       = (const float*)d_in[16];
    const float* b2       = (const float*)d_in[17];
    const float* out_g    = (const float*)d_in[18];
    const float* out_b    = (const float*)d_in[19];
    float* out = (float*)d_out;

    float *x, *pm;
    __half *qkv16, *h16, *att16, *mlp16, *p16, *w16;
    int* s0;
    cudaGetSymbolAddress((void**)&x,     g_x);
    cudaGetSymbolAddress((void**)&pm,    g_pm);
    cudaGetSymbolAddress((void**)&s0,    g_s0);
    cudaGetSymbolAddress((void**)&qkv16, g_qkv16);
    cudaGetSymbolAddress((void**)&h16,   g_h16);
    cudaGetSymbolAddress((void**)&att16, g_att16);
    cudaGetSymbolAddress((void**)&mlp16, g_mlp16);
    cudaGetSymbolAddress((void**)&p16,   g_p16);
    cudaGetSymbolAddress((void**)&w16,   g_w16);

    cudaFuncSetAttribute(attn_kernel, cudaFuncAttributeMaxDynamicSharedMemorySize, ATT_SMEM);
    cudaFuncSetAttribute(tgemm_kernel, cudaFuncAttributeMaxDynamicSharedMemorySize, TG_SMEM);

    __half* qkvT = w16 + OFF_QKVT;
    __half* woT  = w16 + OFF_WOT;
    __half* w1T  = w16 + OFF_W1T;
    __half* w2T  = w16 + OFF_W2T;
    __half* webT = w16 + OFF_WEBT;

    // weight transposes ([K][N] f32 -> [N][Kd] fp16), batched over layers
    dim3 tb(32, 8);
    transpose_kernel<<<dim3(16, 14, 1), tb>>>(W_embed, webT, PDIM, DIM, PDIMP);
    transpose_kernel<<<dim3(48, 16, DEPTH), tb>>>(Wqkv, qkvT, DIM, 3 * DIM, DIM);
    transpose_kernel<<<dim3(16, 16, DEPTH), tb>>>(Wo, woT, DIM, DIM, DIM);
    transpose_kernel<<<dim3(64, 16, DEPTH), tb>>>(W1, w1T, DIM, MLPD, DIM);
    transpose_kernel<<<dim3(16, 64, DEPTH), tb>>>(W2, w2T, MLPD, DIM, MLPD);

    s0_kernel<<<1, 32>>>(done, s0);
    cvt_patch_kernel<<<(TOK * PDIMP / 4) / 256, 256>>>(patch, p16);

    // patch embed + pos embed
    tgemm_kernel<<<dim3(DIM / 128, TOK / 128), 256, TG_SMEM>>>(
        p16, webT, b_embed, nullptr, x, nullptr, TOK, DIM, PDIMP, EPI_EMBED,
        spatial, temporal);

    for (int i = 0; i < DEPTH; ++i) {
        ln_kernel<true><<<TOK / 8, 256>>>(x, ln1_g + (size_t)i * DIM,
                                          ln1_b + (size_t)i * DIM, nullptr, h16);

        tgemm_kernel<<<dim3(3 * DIM / 128, TOK / 128), 256, TG_SMEM>>>(
            h16, qkvT + (size_t)i * 3 * DIM * DIM, bqkv + (size_t)i * 3 * DIM,
            nullptr, nullptr, qkv16, TOK, 3 * DIM, DIM, EPI_NONE, nullptr, nullptr);

        pmean_kernel<<<dim3(8, NB), 512>>>(qkv16, pm);
        attn_kernel<<<dim3((SEQL + AT - 1) / AT, HEADS, NB), 256, ATT_SMEM>>>(
            qkv16, s0, pm, att16);

        tgemm_kernel<<<dim3(DIM / 128, TOK / 128), 256, TG_SMEM>>>(
            att16, woT + (size_t)i * DIM * DIM, bo + (size_t)i * DIM,
            x, x, nullptr, TOK, DIM, DIM, EPI_RES, nullptr, nullptr);

        ln_kernel<true><<<TOK / 8, 256>>>(x, ln2_g + (size_t)i * DIM,
                                          ln2_b + (size_t)i * DIM, nullptr, h16);

        tgemm_kernel<<<dim3(MLPD / 128, TOK / 128), 256, TG_SMEM>>>(
            h16, w1T + (size_t)i * DIM * MLPD, b1 + (size_t)i * MLPD,
            nullptr, nullptr, mlp16, TOK, MLPD, DIM, EPI_GELU, nullptr, nullptr);

        tgemm_kernel<<<dim3(DIM / 128, TOK / 128), 256, TG_SMEM>>>(
            mlp16, w2T + (size_t)i * MLPD * DIM, b2 + (size_t)i * DIM,
            x, x, nullptr, TOK, DIM, MLPD, EPI_RES, nullptr, nullptr);
    }

    ln_kernel<false><<<TOK / 8, 256>>>(x, out_g, out_b, out, nullptr);
}